// round 7
// baseline (speedup 1.0000x reference)
#include <cuda_runtime.h>
#include <cstddef>

// Problem constants (fixed shapes from reference)
#define BTOT 16384   // b*n
#define FIN  2048
#define CIN  128
#define CFF  512
#define COUT 128
#define TPOS 16
#define BM   128     // rows of x per block
#define CH   64      // cff chunk per iteration

// Shared-memory row strides (floats), padded so row stride mod 32 banks == 4
#define SA_S  (CIN + 4)   // 132
#define SW1_S (CIN + 4)   // 132
#define SH_S  (CH + 4)    // 68
#define SW2_S (CH + 4)    // 68

#define SMEM_FLOATS (BM*SA_S + CH*SW1_S + BM*SH_S + COUT*SW2_S)
#define SMEM_BYTES  (SMEM_FLOATS * 4)

// Round fp32 -> tf32 (RNA) so mma sees properly rounded operands (no truncation bias)
__device__ __forceinline__ float tf32r(float x) {
    unsigned r;
    asm("cvt.rna.tf32.f32 %0, %1;" : "=r"(r) : "f"(x));
    return __uint_as_float(r);
}

// Permute k within each aligned 8-group so that fragment pairs (k, k+4) become
// adjacent floats => single conflict-free float2 LDS per fragment pair.
__device__ __forceinline__ int kperm(int k) {
    return (k & ~7) | ((k & 3) << 1) | ((k >> 2) & 1);
}
__device__ __forceinline__ int kperm8(int j) {   // j in [0,8)
    return ((j & 3) << 1) | ((j >> 2) & 1);
}

__device__ __forceinline__ float gelu_exact(float v) {
    return 0.5f * v * (1.0f + erff(v * 0.70710678118654752440f));
}

// mma.sync m16n8k8 tf32, row x col, f32 accumulate
__device__ __forceinline__ void mma_tf32(float c[4], const unsigned a[4],
                                         unsigned b0, unsigned b1) {
    asm volatile(
        "mma.sync.aligned.m16n8k8.row.col.f32.tf32.tf32.f32 "
        "{%0,%1,%2,%3}, {%4,%5,%6,%7}, {%8,%9}, {%0,%1,%2,%3};\n"
        : "+f"(c[0]), "+f"(c[1]), "+f"(c[2]), "+f"(c[3])
        : "r"(a[0]), "r"(a[1]), "r"(a[2]), "r"(a[3]), "r"(b0), "r"(b1));
}

__global__ void __launch_bounds__(256, 1)
jff_fused_kernel(const float* __restrict__ x,
                 const float* __restrict__ w1,
                 const float* __restrict__ w2,
                 float* __restrict__ y)
{
    extern __shared__ float smem[];
    float* sA  = smem;                    // [BM][SA_S]
    float* sW1 = sA  + BM  * SA_S;        // [CH][SW1_S]
    float* sH  = sW1 + CH  * SW1_S;       // [BM][SH_S]
    float* sW2 = sH  + BM  * SH_S;        // [COUT][SW2_S]

    const int t   = blockIdx.x;           // t fastest -> L2 reuse of x across t
    const int m0  = blockIdx.y * BM;
    const int tid = threadIdx.x;
    const int warp  = tid >> 5;
    const int lane  = tid & 31;
    const int group = lane >> 2;          // 0..7 (row within 8)
    const int qp    = lane & 3;           // 0..3 (k quad)

    // Warp tiling:
    //  GEMM1: 4 warps along M (32 rows each) x 2 along N (32 cff each)
    //  GEMM2: same M split, 2 warps along N (64 cout each)
    const int wm = warp & 3;
    const int wn = warp >> 2;

    // ---- Load A tile [BM x CIN] (strided gmem: col stride = TPOS floats) ----
    for (int idx = tid; idx < BM * CIN; idx += 256) {
        const int i = idx >> 7;           // row (CIN=128)
        const int c = idx & 127;          // k
        const float v = x[(size_t)(m0 + i) * FIN + c * TPOS + t];
        sA[i * SA_S + kperm(c)] = tf32r(v);
    }

    // Persistent output accumulators: [2 m-tiles][8 n-tiles][4 regs] = 64 f32
    float acc[2][8][4];
#pragma unroll
    for (int mi = 0; mi < 2; mi++)
#pragma unroll
        for (int ni = 0; ni < 8; ni++)
#pragma unroll
            for (int j = 0; j < 4; j++) acc[mi][ni][j] = 0.0f;

#pragma unroll 1
    for (int ch = 0; ch < CFF / CH; ch++) {
        const int n0 = ch * CH;

        __syncthreads();  // prior chunk's GEMM2 reads of sH/sW2 done; sA ready (iter 0)

        // ---- Load W1 chunk [CH x CIN] ----
        for (int idx = tid; idx < CH * CIN; idx += 256) {
            const int o = idx >> 7, c = idx & 127;
            sW1[o * SW1_S + kperm(c)] =
                tf32r(w1[((size_t)(n0 + o) * CIN + c) * TPOS + t]);
        }
        // ---- Load W2 chunk [COUT x CH] ----
        for (int idx = tid; idx < COUT * CH; idx += 256) {
            const int o = idx >> 6, k = idx & 63;
            sW2[o * SW2_S + kperm(k)] =
                tf32r(w2[((size_t)o * CFF + (n0 + k)) * TPOS + t]);
        }
        __syncthreads();

        // ---- GEMM1: C1[32M x 32N] = A[32M x 128K] * W1chunk^T ----
        float c1[2][4][4];
#pragma unroll
        for (int mi = 0; mi < 2; mi++)
#pragma unroll
            for (int ni = 0; ni < 4; ni++)
#pragma unroll
                for (int j = 0; j < 4; j++) c1[mi][ni][j] = 0.0f;

#pragma unroll
        for (int ks = 0; ks < CIN / 8; ks++) {
            const int kb = ks * 8;
            unsigned a[2][4];
#pragma unroll
            for (int mi = 0; mi < 2; mi++) {
                const int r = wm * 32 + mi * 16 + group;
                const float2 lo = *(const float2*)&sA[r * SA_S + kb + 2 * qp];
                const float2 hi = *(const float2*)&sA[(r + 8) * SA_S + kb + 2 * qp];
                a[mi][0] = __float_as_uint(lo.x);
                a[mi][2] = __float_as_uint(lo.y);
                a[mi][1] = __float_as_uint(hi.x);
                a[mi][3] = __float_as_uint(hi.y);
            }
#pragma unroll
            for (int ni = 0; ni < 4; ni++) {
                const int n = wn * 32 + ni * 8 + group;
                const float2 bb = *(const float2*)&sW1[n * SW1_S + kb + 2 * qp];
                const unsigned b0 = __float_as_uint(bb.x);
                const unsigned b1 = __float_as_uint(bb.y);
#pragma unroll
                for (int mi = 0; mi < 2; mi++) mma_tf32(c1[mi][ni], a[mi], b0, b1);
            }
        }

        // ---- exact GELU -> sH (tf32-rounded, k-permuted for GEMM2) ----
#pragma unroll
        for (int mi = 0; mi < 2; mi++) {
            const int r0 = wm * 32 + mi * 16 + group;
#pragma unroll
            for (int ni = 0; ni < 4; ni++) {
                const int cb = wn * 32 + ni * 8;
                sH[r0 * SH_S + cb + kperm8(2 * qp)] =
                    tf32r(gelu_exact(c1[mi][ni][0]));
                sH[r0 * SH_S + cb + kperm8(2 * qp + 1)] =
                    tf32r(gelu_exact(c1[mi][ni][1]));
                sH[(r0 + 8) * SH_S + cb + kperm8(2 * qp)] =
                    tf32r(gelu_exact(c1[mi][ni][2]));
                sH[(r0 + 8) * SH_S + cb + kperm8(2 * qp + 1)] =
                    tf32r(gelu_exact(c1[mi][ni][3]));
            }
        }
        __syncthreads();

        // ---- GEMM2: acc[32M x 64N] += H[32M x 64K] * W2chunk^T ----
#pragma unroll
        for (int ks = 0; ks < CH / 8; ks++) {
            const int kb = ks * 8;
            unsigned a[2][4];
#pragma unroll
            for (int mi = 0; mi < 2; mi++) {
                const int r = wm * 32 + mi * 16 + group;
                const float2 lo = *(const float2*)&sH[r * SH_S + kb + 2 * qp];
                const float2 hi = *(const float2*)&sH[(r + 8) * SH_S + kb + 2 * qp];
                a[mi][0] = __float_as_uint(lo.x);
                a[mi][2] = __float_as_uint(lo.y);
                a[mi][1] = __float_as_uint(hi.x);
                a[mi][3] = __float_as_uint(hi.y);
            }
#pragma unroll
            for (int ni = 0; ni < 8; ni++) {
                const int n = wn * 64 + ni * 8 + group;
                const float2 bb = *(const float2*)&sW2[n * SW2_S + kb + 2 * qp];
                const unsigned b0 = __float_as_uint(bb.x);
                const unsigned b1 = __float_as_uint(bb.y);
#pragma unroll
                for (int mi = 0; mi < 2; mi++) mma_tf32(acc[mi][ni], a[mi], b0, b1);
            }
        }
    }

    // ---- Epilogue: scatter Y back to strided feature layout (o*T + t) ----
#pragma unroll
    for (int mi = 0; mi < 2; mi++) {
        const size_t r0 = (size_t)(m0 + wm * 32 + mi * 16 + group);
        const size_t r1 = r0 + 8;
#pragma unroll
        for (int ni = 0; ni < 8; ni++) {
            const int o0 = wn * 64 + ni * 8 + 2 * qp;
            y[r0 * FIN + (size_t)o0 * TPOS + t]       = acc[mi][ni][0];
            y[r0 * FIN + (size_t)(o0 + 1) * TPOS + t] = acc[mi][ni][1];
            y[r1 * FIN + (size_t)o0 * TPOS + t]       = acc[mi][ni][2];
            y[r1 * FIN + (size_t)(o0 + 1) * TPOS + t] = acc[mi][ni][3];
        }
    }
}

extern "C" void kernel_launch(void* const* d_in, const int* in_sizes, int n_in,
                              void* d_out, int out_size)
{
    const float* x  = (const float*)d_in[0];   // [64,256,2048] fp32
    const float* w1 = (const float*)d_in[1];   // [512,128,16] fp32
    const float* w2 = (const float*)d_in[2];   // [128,512,16] fp32
    float* y = (float*)d_out;                  // [64,256,2048] fp32
    (void)in_sizes; (void)n_in; (void)out_size;

    cudaFuncSetAttribute(jff_fused_kernel,
                         cudaFuncAttributeMaxDynamicSharedMemorySize, SMEM_BYTES);

    dim3 grid(TPOS, BTOT / BM);   // t fastest: 16 t-blocks of one m-tile share x in L2
    jff_fused_kernel<<<grid, 256, SMEM_BYTES>>>(x, w1, w2, y);
}

// round 8
// speedup vs baseline: 1.9017x; 1.9017x over previous
#include <cuda_runtime.h>
#include <cstddef>

// Problem constants (fixed shapes)
#define BTOT 16384   // b*n
#define FIN  2048
#define CIN  128
#define CFF  512
#define COUT 128
#define TPOS 16
#define BM   128     // rows of x per block
#define CH   64      // cff chunk per iteration

// k-major shared layouts. Row strides chosen ≡ 8 (mod 32) so fragment LDS.32
// banks = 8*qp + group -> all 32 lanes distinct -> conflict-free.
#define SR_A  136    // sA  [CIN k][BM r]    stride (8 mod 32, /4 for float4)
#define SN_W1 72     // sW1 [CIN k][CH n]    stride
#define SR_H  136    // sH  [CH k][BM r]     stride
#define SN_W2 136    // sW2 [CH k][COUT o]   stride
#define OS    132    // epilogue sOut [COUT o][BM r] stride (banks 8q+g, float4-aligned)

#define SMEM_FLOATS (CIN*SR_A + CIN*SN_W1 + CH*SR_H + CH*SN_W2)
#define SMEM_BYTES  (SMEM_FLOATS * 4)   // 176128 B

// Scratch (device globals: allocation-free rule)
__device__ float g_xT [2048ull * 16384];   // xT[f][row],  f = c*16+t
__device__ float g_yT [2048ull * 16384];   // yT[f][row],  f = o*16+t
__device__ float g_w1t[2048 * 512];        // w1t[(c*16+t)][o]
__device__ float g_w2t[8192 * 128];        // w2t[(k*16+t)][o]

__device__ __forceinline__ float tf32r(float x) {
    unsigned r;
    asm("cvt.rna.tf32.f32 %0, %1;" : "=r"(r) : "f"(x));
    return __uint_as_float(r);
}

__device__ __forceinline__ float gelu_exact(float v) {
    return 0.5f * v * (1.0f + erff(v * 0.70710678118654752440f));
}

__device__ __forceinline__ void mma_tf32(float c[4], const unsigned a[4],
                                         unsigned b0, unsigned b1) {
    asm volatile(
        "mma.sync.aligned.m16n8k8.row.col.f32.tf32.tf32.f32 "
        "{%0,%1,%2,%3}, {%4,%5,%6,%7}, {%8,%9}, {%0,%1,%2,%3};\n"
        : "+f"(c[0]), "+f"(c[1]), "+f"(c[2]), "+f"(c[3])
        : "r"(a[0]), "r"(a[1]), "r"(a[2]), "r"(a[3]), "r"(b0), "r"(b1));
}

// ---------------- Generic tiled transpose: out[C][R] = in[R][C]^T -------------
__global__ void transpose_kernel(float* __restrict__ out, const float* __restrict__ in,
                                 int R, int C) {
    __shared__ float tile[32][33];
    const int bx = blockIdx.x * 32;   // C offset
    const int by = blockIdx.y * 32;   // R offset
    const int x  = threadIdx.x & 31;
    const int y0 = threadIdx.x >> 5;  // 0..7
#pragma unroll
    for (int j = 0; j < 32; j += 8) {
        const int r = by + y0 + j, c = bx + x;
        if (r < R && c < C) tile[y0 + j][x] = in[(size_t)r * C + c];
    }
    __syncthreads();
#pragma unroll
    for (int j = 0; j < 32; j += 8) {
        const int c = bx + y0 + j, r = by + x;
        if (c < C && r < R) out[(size_t)c * R + r] = tile[x][y0 + j];
    }
}

// ------------------------------- Main fused kernel ----------------------------
__global__ void __launch_bounds__(256, 1)
jff_fused_kernel(const float* __restrict__ xT,
                 const float* __restrict__ w1t,
                 const float* __restrict__ w2t,
                 float* __restrict__ yT)
{
    extern __shared__ float smem[];
    float* sA  = smem;                   // [CIN][SR_A]
    float* sW1 = sA  + CIN * SR_A;       // [CIN][SN_W1]
    float* sH  = sW1 + CIN * SN_W1;      // [CH][SR_H]
    float* sW2 = sH  + CH  * SR_H;       // [CH][SN_W2]

    const int t   = blockIdx.x;          // t fastest -> L2 reuse across t
    const int m0  = blockIdx.y * BM;
    const int tid = threadIdx.x;
    const int warp  = tid >> 5;
    const int lane  = tid & 31;
    const int group = lane >> 2;         // 0..7
    const int qp    = lane & 3;          // 0..3
    const int wm = warp & 3;             // 4 warps along M (32 rows each)
    const int wn = warp >> 2;            // 2 warps along N

    // ---- Stage A tile: xT[f][row] -> sA[c][r], float4 coalesced both sides ----
    for (int idx = tid; idx < CIN * (BM / 4); idx += 256) {
        const int c  = idx >> 5;         // 0..127
        const int rq = idx & 31;         // float4 group along rows
        float4 v = *(const float4*)&xT[(size_t)(c * TPOS + t) * BTOT + m0 + 4 * rq];
        v.x = tf32r(v.x); v.y = tf32r(v.y); v.z = tf32r(v.z); v.w = tf32r(v.w);
        *(float4*)&sA[c * SR_A + 4 * rq] = v;
    }

    // Persistent GEMM2 accumulators: [2 m][8 n][4]
    float acc[2][8][4];
#pragma unroll
    for (int mi = 0; mi < 2; mi++)
#pragma unroll
        for (int ni = 0; ni < 8; ni++)
#pragma unroll
            for (int j = 0; j < 4; j++) acc[mi][ni][j] = 0.0f;

#pragma unroll 1
    for (int ch = 0; ch < CFF / CH; ch++) {
        const int n0 = ch * CH;

        __syncthreads();   // prior GEMM2 done reading sH/sW2; sA ready (iter 0)

        // ---- Stage W1 chunk: w1t[(c,t)][o] -> sW1[c][n], coalesced ----
        for (int idx = tid; idx < CIN * (CH / 4); idx += 256) {
            const int c  = idx >> 4;     // 0..127
            const int oq = idx & 15;
            float4 v = *(const float4*)&w1t[(size_t)(c * TPOS + t) * CFF + n0 + 4 * oq];
            v.x = tf32r(v.x); v.y = tf32r(v.y); v.z = tf32r(v.z); v.w = tf32r(v.w);
            *(float4*)&sW1[c * SN_W1 + 4 * oq] = v;
        }
        // ---- Stage W2 chunk: w2t[(k,t)][o] -> sW2[k][o], coalesced ----
        for (int idx = tid; idx < CH * (COUT / 4); idx += 256) {
            const int k  = idx >> 5;     // 0..63
            const int oq = idx & 31;
            float4 v = *(const float4*)&w2t[(size_t)((n0 + k) * TPOS + t) * COUT + 4 * oq];
            v.x = tf32r(v.x); v.y = tf32r(v.y); v.z = tf32r(v.z); v.w = tf32r(v.w);
            *(float4*)&sW2[k * SN_W2 + 4 * oq] = v;
        }
        __syncthreads();

        // ---- GEMM1: C1[32M x 32N] = A * W1^T  (conflict-free LDS.32 frags) ----
        float c1[2][4][4];
#pragma unroll
        for (int mi = 0; mi < 2; mi++)
#pragma unroll
            for (int ni = 0; ni < 4; ni++)
#pragma unroll
                for (int j = 0; j < 4; j++) c1[mi][ni][j] = 0.0f;

#pragma unroll
        for (int ks = 0; ks < CIN / 8; ks++) {
            const int kb = ks * 8;
            unsigned a[2][4];
#pragma unroll
            for (int mi = 0; mi < 2; mi++) {
                const int r = wm * 32 + mi * 16 + group;
                a[mi][0] = __float_as_uint(sA[(kb + qp) * SR_A + r]);
                a[mi][1] = __float_as_uint(sA[(kb + qp) * SR_A + r + 8]);
                a[mi][2] = __float_as_uint(sA[(kb + qp + 4) * SR_A + r]);
                a[mi][3] = __float_as_uint(sA[(kb + qp + 4) * SR_A + r + 8]);
            }
#pragma unroll
            for (int ni = 0; ni < 4; ni++) {
                const int n = wn * 32 + ni * 8 + group;
                const unsigned b0 = __float_as_uint(sW1[(kb + qp) * SN_W1 + n]);
                const unsigned b1 = __float_as_uint(sW1[(kb + qp + 4) * SN_W1 + n]);
#pragma unroll
                for (int mi = 0; mi < 2; mi++) mma_tf32(c1[mi][ni], a[mi], b0, b1);
            }
        }

        // ---- exact GELU -> sH[n][r]  (n becomes k of GEMM2) ----
#pragma unroll
        for (int mi = 0; mi < 2; mi++) {
            const int r0 = wm * 32 + mi * 16 + group;
#pragma unroll
            for (int ni = 0; ni < 4; ni++) {
                const int nb = wn * 32 + ni * 8 + 2 * qp;
                sH[nb * SR_H + r0]           = tf32r(gelu_exact(c1[mi][ni][0]));
                sH[(nb + 1) * SR_H + r0]     = tf32r(gelu_exact(c1[mi][ni][1]));
                sH[nb * SR_H + r0 + 8]       = tf32r(gelu_exact(c1[mi][ni][2]));
                sH[(nb + 1) * SR_H + r0 + 8] = tf32r(gelu_exact(c1[mi][ni][3]));
            }
        }
        __syncthreads();

        // ---- GEMM2: acc[32M x 64N] += H * W2^T ----
#pragma unroll
        for (int ks = 0; ks < CH / 8; ks++) {
            const int kb = ks * 8;
            unsigned a[2][4];
#pragma unroll
            for (int mi = 0; mi < 2; mi++) {
                const int r = wm * 32 + mi * 16 + group;
                a[mi][0] = __float_as_uint(sH[(kb + qp) * SR_H + r]);
                a[mi][1] = __float_as_uint(sH[(kb + qp) * SR_H + r + 8]);
                a[mi][2] = __float_as_uint(sH[(kb + qp + 4) * SR_H + r]);
                a[mi][3] = __float_as_uint(sH[(kb + qp + 4) * SR_H + r + 8]);
            }
#pragma unroll
            for (int ni = 0; ni < 8; ni++) {
                const int o = wn * 64 + ni * 8 + group;
                const unsigned b0 = __float_as_uint(sW2[(kb + qp) * SN_W2 + o]);
                const unsigned b1 = __float_as_uint(sW2[(kb + qp + 4) * SN_W2 + o]);
#pragma unroll
                for (int mi = 0; mi < 2; mi++) mma_tf32(acc[mi][ni], a[mi], b0, b1);
            }
        }
    }

    // ---- Epilogue: regs -> smem [o][r] (conflict-free) -> coalesced yT stores ----
    __syncthreads();
    float* sO = smem;   // reuse sA region: 128*132 = 16896 <= 17408 floats
#pragma unroll
    for (int mi = 0; mi < 2; mi++) {
        const int r0 = wm * 32 + mi * 16 + group;
#pragma unroll
        for (int ni = 0; ni < 8; ni++) {
            const int o0 = wn * 64 + ni * 8 + 2 * qp;
            sO[o0 * OS + r0]           = acc[mi][ni][0];
            sO[(o0 + 1) * OS + r0]     = acc[mi][ni][1];
            sO[o0 * OS + r0 + 8]       = acc[mi][ni][2];
            sO[(o0 + 1) * OS + r0 + 8] = acc[mi][ni][3];
        }
    }
    __syncthreads();
    for (int idx = tid; idx < COUT * (BM / 4); idx += 256) {
        const int o  = idx >> 5;
        const int rq = idx & 31;
        const float4 v = *(const float4*)&sO[o * OS + 4 * rq];
        *(float4*)&yT[(size_t)(o * TPOS + t) * BTOT + m0 + 4 * rq] = v;
    }
}

extern "C" void kernel_launch(void* const* d_in, const int* in_sizes, int n_in,
                              void* d_out, int out_size)
{
    const float* x  = (const float*)d_in[0];   // [16384, 2048] fp32
    const float* w1 = (const float*)d_in[1];   // [512,128,16]  fp32
    const float* w2 = (const float*)d_in[2];   // [128,512,16]  fp32
    float* y = (float*)d_out;                  // [16384, 2048] fp32
    (void)in_sizes; (void)n_in; (void)out_size;

    float *xT, *yT, *w1t, *w2t;
    cudaGetSymbolAddress((void**)&xT,  g_xT);
    cudaGetSymbolAddress((void**)&yT,  g_yT);
    cudaGetSymbolAddress((void**)&w1t, g_w1t);
    cudaGetSymbolAddress((void**)&w2t, g_w2t);

    cudaFuncSetAttribute(jff_fused_kernel,
                         cudaFuncAttributeMaxDynamicSharedMemorySize, SMEM_BYTES);

    // 1) Layout transforms (all coalesced tiled transposes)
    transpose_kernel<<<dim3(FIN / 32, BTOT / 32), 256>>>(xT, x, BTOT, FIN);        // x -> xT[f][row]
    transpose_kernel<<<dim3(2048 / 32, 512 / 32), 256>>>(w1t, w1, CFF, CIN * TPOS); // w1 -> [(c,t)][o]
    transpose_kernel<<<dim3(8192 / 32, 128 / 32), 256>>>(w2t, w2, COUT, CFF * TPOS);// w2 -> [(k,t)][o]

    // 2) Fused locally-connected FFN (writes yT[f][row])
    dim3 grid(TPOS, BTOT / BM);
    jff_fused_kernel<<<grid, 256, SMEM_BYTES>>>(xT, w1t, w2t, yT);

    // 3) yT -> y
    transpose_kernel<<<dim3(BTOT / 32, FIN / 32), 256>>>(y, yT, FIN, BTOT);
}